// round 2
// baseline (speedup 1.0000x reference)
#include <cuda_runtime.h>
#include <math.h>

// Problem constants (fixed by the dataset)
#define N_NODES 50000
#define DIM     128
#define N_EDGES 640000

// GEMM tiling
#define TM 64
#define GEMM_SMEM (DIM*DIM*4 + TM*132*4)   // sW (64KB) + padded sA (33KB) = 99328 B

// ---------------- scratch (device globals; no allocation allowed) ----------------
__device__ float g_hW[N_NODES*DIM];
__device__ float g_y1[N_NODES*DIM];
__device__ float g_z [N_NODES*DIM];
__device__ float g_y2[N_NODES*DIM];
__device__ int   g_rowptr[N_NODES+1];
__device__ float g_s1[DIM], g_t1[DIM], g_s2[DIM], g_t2[DIM];

// ---------------- BN folding: s = gamma*rsqrt(var+eps), t = beta - mean*s --------
__global__ void prep_bn(const float* __restrict__ g1, const float* __restrict__ b1,
                        const float* __restrict__ m1, const float* __restrict__ v1,
                        const float* __restrict__ g2, const float* __restrict__ b2,
                        const float* __restrict__ m2, const float* __restrict__ v2)
{
    int d = threadIdx.x;
    float s1 = g1[d] * rsqrtf(v1[d] + 1e-3f);
    g_s1[d] = s1; g_t1[d] = b1[d] - m1[d] * s1;
    float s2 = g2[d] * rsqrtf(v2[d] + 1e-3f);
    g_s2[d] = s2; g_t2[d] = b2[d] - m2[d] * s2;
}

// ---------------- rowptr: rows is sorted; lower_bound per destination row -------
__global__ void build_rowptr(const int* __restrict__ rows, int n, int e)
{
    int r = blockIdx.x * blockDim.x + threadIdx.x;
    if (r > n) return;
    int lo = 0, hi = e;
    while (lo < hi) {
        int mid = (lo + hi) >> 1;
        if (rows[mid] < r) lo = mid + 1; else hi = mid;
    }
    g_rowptr[r] = lo;
}

// ---------------- C[n,128] = (optional BN(A)) @ W (+ optional bias) -------------
// Block: 256 threads, TM=64 rows, all 128 cols. W cached fully in smem.
__global__ void gemm128(const float* __restrict__ A, const float* __restrict__ W,
                        float* __restrict__ C,
                        const float* __restrict__ bn_s, const float* __restrict__ bn_t,
                        const float* __restrict__ bias, int n)
{
    extern __shared__ float sh[];
    float* sW = sh;                  // [128][128]
    float* sA = sh + DIM * DIM;      // [TM][132] (pad kills bank conflicts)

    const int tid = threadIdx.x;
    const int r0  = blockIdx.x * TM;

    // load W: 4096 float4 / 256 threads = 16 each
    const float4* W4 = (const float4*)W;
    #pragma unroll
    for (int k = 0; k < 16; k++) {
        int idx = tid + k * 256;          // float4 index
        float4 w = W4[idx];
        int row = idx >> 5, c4 = idx & 31;
        *(float4*)&sW[row * DIM + c4 * 4] = w;
    }
    // load A tile (2048 float4), fold BN on the fly
    #pragma unroll
    for (int k = 0; k < 8; k++) {
        int idx = tid + k * 256;
        int row = idx >> 5, c4 = idx & 31;
        int gr = r0 + row;
        float4 a = make_float4(0.f, 0.f, 0.f, 0.f);
        if (gr < n) {
            a = ((const float4*)A)[gr * 32 + c4];
            if (bn_s) {
                int d = c4 * 4;
                a.x = a.x * bn_s[d + 0] + bn_t[d + 0];
                a.y = a.y * bn_s[d + 1] + bn_t[d + 1];
                a.z = a.z * bn_s[d + 2] + bn_t[d + 2];
                a.w = a.w * bn_s[d + 3] + bn_t[d + 3];
            }
        }
        *(float4*)&sA[row * 132 + c4 * 4] = a;
    }
    __syncthreads();

    const int tx = tid & 15;   // 16 col-groups of 8
    const int ty = tid >> 4;   // 16 row-groups of 4
    float acc[4][8];
    #pragma unroll
    for (int i = 0; i < 4; i++)
        #pragma unroll
        for (int j = 0; j < 8; j++) acc[i][j] = 0.f;

    #pragma unroll 4
    for (int k = 0; k < DIM; k++) {
        float av[4];
        #pragma unroll
        for (int i = 0; i < 4; i++) av[i] = sA[(ty * 4 + i) * 132 + k];
        float4 w0 = *(float4*)&sW[k * DIM + tx * 8];
        float4 w1 = *(float4*)&sW[k * DIM + tx * 8 + 4];
        float wv[8] = {w0.x, w0.y, w0.z, w0.w, w1.x, w1.y, w1.z, w1.w};
        #pragma unroll
        for (int i = 0; i < 4; i++)
            #pragma unroll
            for (int j = 0; j < 8; j++) acc[i][j] += av[i] * wv[j];
    }

    float bsv[8] = {0.f,0.f,0.f,0.f,0.f,0.f,0.f,0.f};
    if (bias) {
        float4 b0 = ((const float4*)bias)[tx * 2];
        float4 b1v = ((const float4*)bias)[tx * 2 + 1];
        bsv[0]=b0.x; bsv[1]=b0.y; bsv[2]=b0.z; bsv[3]=b0.w;
        bsv[4]=b1v.x; bsv[5]=b1v.y; bsv[6]=b1v.z; bsv[7]=b1v.w;
    }
    #pragma unroll
    for (int i = 0; i < 4; i++) {
        int r = r0 + ty * 4 + i;
        if (r >= n) continue;
        float4 o0 = make_float4(acc[i][0]+bsv[0], acc[i][1]+bsv[1], acc[i][2]+bsv[2], acc[i][3]+bsv[3]);
        float4 o1 = make_float4(acc[i][4]+bsv[4], acc[i][5]+bsv[5], acc[i][6]+bsv[6], acc[i][7]+bsv[7]);
        ((float4*)C)[r * 32 + tx * 2]     = o0;
        ((float4*)C)[r * 32 + tx * 2 + 1] = o1;
    }
}

// ---------------- y1 = tanh(A @ hW + b1): warp per destination row --------------
__global__ void spmm_tanh(const float* __restrict__ hW, const int* __restrict__ cols,
                          const float* __restrict__ vals, const float* __restrict__ b1,
                          float* __restrict__ y1, int n)
{
    int w = (blockIdx.x * blockDim.x + threadIdx.x) >> 5;
    int lane = threadIdx.x & 31;
    if (w >= n) return;
    int s = g_rowptr[w], e = g_rowptr[w + 1];
    const float4* H = (const float4*)hW;
    float4 acc = make_float4(0.f, 0.f, 0.f, 0.f);
    for (int i = s; i < e; i++) {
        int   c = __ldg(&cols[i]);
        float v = __ldg(&vals[i]);
        float4 h = H[c * 32 + lane];
        acc.x += v * h.x; acc.y += v * h.y; acc.z += v * h.z; acc.w += v * h.w;
    }
    float4 b = ((const float4*)b1)[lane];
    float4 o = make_float4(tanhf(acc.x + b.x), tanhf(acc.y + b.y),
                           tanhf(acc.z + b.z), tanhf(acc.w + b.w));
    ((float4*)y1)[w * 32 + lane] = o;
}

// ---------------- z = A_rel @ BN2(y1) + BN2(y1)*(ck+1)  (BN2 hoisted) -----------
// sum_e ev*BN2(y1[c]) = s2 * (sum ev*y1[c]) + t2 * (sum ev)
__global__ void spmm_rgin(const float* __restrict__ y1, const int* __restrict__ cols,
                          const float* __restrict__ vals, const int* __restrict__ rel,
                          const float* __restrict__ relc, const float* __restrict__ ck,
                          float* __restrict__ z, int n)
{
    int w = (blockIdx.x * blockDim.x + threadIdx.x) >> 5;
    int lane = threadIdx.x & 31;
    if (w >= n) return;
    int s = g_rowptr[w], e = g_rowptr[w + 1];
    const float4* Y = (const float4*)y1;
    float4 accA = make_float4(0.f, 0.f, 0.f, 0.f);
    float  accB = 0.f;
    for (int i = s; i < e; i++) {
        float ev = __ldg(&vals[i]) / (__ldg(&relc[__ldg(&rel[i])]) + 1.f);
        int c = __ldg(&cols[i]);
        float4 h = Y[c * 32 + lane];
        accA.x += ev * h.x; accA.y += ev * h.y;
        accA.z += ev * h.z; accA.w += ev * h.w;
        accB += ev;
    }
    int d = lane * 4;
    float4 s2 = *(const float4*)&g_s2[d];
    float4 t2 = *(const float4*)&g_t2[d];
    float4 yr = Y[w * 32 + lane];
    float  cm = __ldg(&ck[w]) + 1.f;
    float4 o;
    o.x = s2.x * accA.x + t2.x * accB + (yr.x * s2.x + t2.x) * cm;
    o.y = s2.y * accA.y + t2.y * accB + (yr.y * s2.y + t2.y) * cm;
    o.z = s2.z * accA.z + t2.z * accB + (yr.z * s2.z + t2.z) * cm;
    o.w = s2.w * accA.w + t2.w * accB + (yr.w * s2.w + t2.w) * cm;
    ((float4*)z)[w * 32 + lane] = o;
}

// ---------------- out = l2n(concat(l2n(x), l2n(y1), l2n(y2))) -------------------
__global__ void final_norm(const float* __restrict__ x, const float* __restrict__ y1,
                           const float* __restrict__ y2, float* __restrict__ out, int n)
{
    int w = (blockIdx.x * blockDim.x + threadIdx.x) >> 5;
    int lane = threadIdx.x & 31;
    if (w >= n) return;
    float4 a = ((const float4*)x )[w * 32 + lane];
    float4 b = ((const float4*)y1)[w * 32 + lane];
    float4 c = ((const float4*)y2)[w * 32 + lane];
    float sa = a.x*a.x + a.y*a.y + a.z*a.z + a.w*a.w;
    float sb = b.x*b.x + b.y*b.y + b.z*b.z + b.w*b.w;
    float sc = c.x*c.x + c.y*c.y + c.z*c.z + c.w*c.w;
    #pragma unroll
    for (int o = 16; o; o >>= 1) {
        sa += __shfl_xor_sync(0xffffffffu, sa, o);
        sb += __shfl_xor_sync(0xffffffffu, sb, o);
        sc += __shfl_xor_sync(0xffffffffu, sc, o);
    }
    float ra = rsqrtf(fmaxf(sa, 1e-12f));
    float rb = rsqrtf(fmaxf(sb, 1e-12f));
    float rc = rsqrtf(fmaxf(sc, 1e-12f));
    // squared norm of each normalized part (==1 unless degenerate)
    float na = sa * ra * ra, nb = sb * rb * rb, nc = sc * rc * rc;
    float rt = rsqrtf(fmaxf(na + nb + nc, 1e-12f));
    float fa = ra * rt, fb = rb * rt, fc = rc * rt;
    float4* O = (float4*)out;
    int base = w * 96;                 // 384 floats = 96 float4 per row
    O[base + lane]      = make_float4(a.x*fa, a.y*fa, a.z*fa, a.w*fa);
    O[base + 32 + lane] = make_float4(b.x*fb, b.y*fb, b.z*fb, b.w*fb);
    O[base + 64 + lane] = make_float4(c.x*fc, c.y*fc, c.z*fc, c.w*fc);
}

// ---------------- launch --------------------------------------------------------
extern "C" void kernel_launch(void* const* d_in, const int* in_sizes, int n_in,
                              void* d_out, int out_size)
{
    const float* x      = (const float*)d_in[0];
    const int*   rows   = (const int*)  d_in[1];
    const int*   cols   = (const int*)  d_in[2];
    const float* adj    = (const float*)d_in[3];
    const int*   rel    = (const int*)  d_in[4];
    const float* gamma1 = (const float*)d_in[5];
    const float* beta1  = (const float*)d_in[6];
    const float* mean1  = (const float*)d_in[7];
    const float* var1   = (const float*)d_in[8];
    const float* W1     = (const float*)d_in[9];
    const float* b1     = (const float*)d_in[10];
    const float* gamma2 = (const float*)d_in[11];
    const float* beta2  = (const float*)d_in[12];
    const float* mean2  = (const float*)d_in[13];
    const float* var2   = (const float*)d_in[14];
    const float* relc   = (const float*)d_in[15];
    const float* ck     = (const float*)d_in[16];
    const float* Wd     = (const float*)d_in[17];
    const float* bd     = (const float*)d_in[18];
    float* out = (float*)d_out;

    const int n = in_sizes[0] / DIM;     // 50000
    const int e = in_sizes[1];           // 640000

    cudaFuncSetAttribute(gemm128, cudaFuncAttributeMaxDynamicSharedMemorySize, GEMM_SMEM);

    // IMPORTANT: __device__ symbols are NOT valid host-side pointers.
    // Fetch the real device addresses and pass those.
    float *hW, *y1, *z, *y2, *s1, *t1;
    cudaGetSymbolAddress((void**)&hW, g_hW);
    cudaGetSymbolAddress((void**)&y1, g_y1);
    cudaGetSymbolAddress((void**)&z,  g_z);
    cudaGetSymbolAddress((void**)&y2, g_y2);
    cudaGetSymbolAddress((void**)&s1, g_s1);
    cudaGetSymbolAddress((void**)&t1, g_t1);

    prep_bn<<<1, DIM>>>(gamma1, beta1, mean1, var1, gamma2, beta2, mean2, var2);
    build_rowptr<<<(n + 1 + 255) / 256, 256>>>(rows, n, e);

    int gemm_blocks = (n + TM - 1) / TM;
    gemm128<<<gemm_blocks, 256, GEMM_SMEM>>>(x, W1, hW, s1, t1, nullptr, n);

    int warp_blocks = (n * 32 + 255) / 256;
    spmm_tanh<<<warp_blocks, 256>>>(hW, cols, adj, b1, y1, n);
    spmm_rgin<<<warp_blocks, 256>>>(y1, cols, adj, rel, relc, ck, z, n);

    gemm128<<<gemm_blocks, 256, GEMM_SMEM>>>(z, Wd, y2, nullptr, nullptr, bd, n);

    final_norm<<<warp_blocks, 256>>>(x, y1, y2, out, n);
}

// round 3
// speedup vs baseline: 1.2489x; 1.2489x over previous
#include <cuda_runtime.h>
#include <mma.h>
#include <math.h>

using namespace nvcuda;

// Problem constants (fixed by the dataset)
#define N_NODES 50000
#define DIM     128
#define N_EDGES 640000

// GEMM tiling: block computes 64 rows x 128 cols with tf32 wmma
#define TM 64
#define LDS_PAD 136                       // padded leading dim (mult of 8)
#define GEMM_SMEM ((DIM*LDS_PAD + TM*LDS_PAD) * 4)   // sW 69632 + sA 34816 = 104448 B

// ---------------- scratch (device globals; no allocation allowed) ----------------
__device__ float g_hW[N_NODES*DIM];
__device__ float g_y1[N_NODES*DIM];
__device__ float g_z [N_NODES*DIM];
__device__ float g_y2[N_NODES*DIM];
__device__ int   g_rowptr[N_NODES+1];
__device__ float g_s1[DIM], g_t1[DIM], g_s2[DIM], g_t2[DIM];

// ---------------- BN folding: s = gamma*rsqrt(var+eps), t = beta - mean*s --------
__global__ void prep_bn(const float* __restrict__ g1, const float* __restrict__ b1,
                        const float* __restrict__ m1, const float* __restrict__ v1,
                        const float* __restrict__ g2, const float* __restrict__ b2,
                        const float* __restrict__ m2, const float* __restrict__ v2)
{
    int d = threadIdx.x;
    float s1 = g1[d] * rsqrtf(v1[d] + 1e-3f);
    g_s1[d] = s1; g_t1[d] = b1[d] - m1[d] * s1;
    float s2 = g2[d] * rsqrtf(v2[d] + 1e-3f);
    g_s2[d] = s2; g_t2[d] = b2[d] - m2[d] * s2;
}

// ---------------- rowptr: rows is sorted; lower_bound per destination row -------
__global__ void build_rowptr(const int* __restrict__ rows, int n, int e)
{
    int r = blockIdx.x * blockDim.x + threadIdx.x;
    if (r > n) return;
    int lo = 0, hi = e;
    while (lo < hi) {
        int mid = (lo + hi) >> 1;
        if (rows[mid] < r) lo = mid + 1; else hi = mid;
    }
    g_rowptr[r] = lo;
}

// ---------------- C[n,128] = (optional BN(A)) @ W (+ optional bias), tf32 wmma --
// Block: 256 threads = 8 warps. Warp (wr, wc): rows wr*16..+16, cols wc*64..+64.
__global__ void __launch_bounds__(256, 2)
gemm128_tf32(const float* __restrict__ A, const float* __restrict__ W,
             float* __restrict__ C,
             const float* __restrict__ bn_s, const float* __restrict__ bn_t,
             const float* __restrict__ bias, int n)
{
    extern __shared__ float sh[];
    float* sW = sh;                       // [128][136]
    float* sA = sh + DIM * LDS_PAD;       // [64][136]  (also reused as epilogue buf)

    const int tid = threadIdx.x;
    const int r0  = blockIdx.x * TM;

    // ---- load W into smem (rounded to tf32 once) : 4096 float4 / 256 thr ------
    const float4* W4 = (const float4*)W;
    #pragma unroll
    for (int k = 0; k < 16; k++) {
        int idx = tid + k * 256;          // float4 index over 128x128
        float4 w = W4[idx];
        w.x = wmma::__float_to_tf32(w.x);
        w.y = wmma::__float_to_tf32(w.y);
        w.z = wmma::__float_to_tf32(w.z);
        w.w = wmma::__float_to_tf32(w.w);
        int row = idx >> 5, c4 = idx & 31;
        *(float4*)&sW[row * LDS_PAD + c4 * 4] = w;
    }
    // ---- load A tile (fold BN, round to tf32) : 2048 float4 -------------------
    #pragma unroll
    for (int k = 0; k < 8; k++) {
        int idx = tid + k * 256;
        int row = idx >> 5, c4 = idx & 31;
        int gr = r0 + row;
        float4 a = make_float4(0.f, 0.f, 0.f, 0.f);
        if (gr < n) {
            a = ((const float4*)A)[gr * 32 + c4];
            if (bn_s) {
                int d = c4 * 4;
                a.x = a.x * bn_s[d + 0] + bn_t[d + 0];
                a.y = a.y * bn_s[d + 1] + bn_t[d + 1];
                a.z = a.z * bn_s[d + 2] + bn_t[d + 2];
                a.w = a.w * bn_s[d + 3] + bn_t[d + 3];
            }
            a.x = wmma::__float_to_tf32(a.x);
            a.y = wmma::__float_to_tf32(a.y);
            a.z = wmma::__float_to_tf32(a.z);
            a.w = wmma::__float_to_tf32(a.w);
        }
        *(float4*)&sA[row * LDS_PAD + c4 * 4] = a;
    }
    __syncthreads();

    const int wid = tid >> 5;
    const int wr  = wid >> 1;            // 0..3 : 16-row group
    const int wc  = wid & 1;             // 0..1 : 64-col group

    wmma::fragment<wmma::accumulator, 16, 16, 8, float> acc[4];
    #pragma unroll
    for (int j = 0; j < 4; j++) wmma::fill_fragment(acc[j], 0.f);

    #pragma unroll
    for (int kk = 0; kk < DIM; kk += 8) {
        wmma::fragment<wmma::matrix_a, 16, 16, 8, wmma::precision::tf32, wmma::row_major> af;
        wmma::load_matrix_sync(af, &sA[(wr * 16) * LDS_PAD + kk], LDS_PAD);
        #pragma unroll
        for (int j = 0; j < 4; j++) {
            wmma::fragment<wmma::matrix_b, 16, 16, 8, wmma::precision::tf32, wmma::row_major> bf;
            wmma::load_matrix_sync(bf, &sW[kk * LDS_PAD + wc * 64 + j * 16], LDS_PAD);
            wmma::mma_sync(acc[j], af, bf, acc[j]);
        }
    }

    // ---- epilogue: park accumulators in smem (reuse sA), add bias, store ------
    __syncthreads();   // everyone done reading sA
    #pragma unroll
    for (int j = 0; j < 4; j++)
        wmma::store_matrix_sync(&sA[(wr * 16) * LDS_PAD + wc * 64 + j * 16],
                                acc[j], LDS_PAD, wmma::mem_row_major);
    __syncthreads();

    #pragma unroll
    for (int k = 0; k < 8; k++) {
        int idx = tid + k * 256;          // 2048 float4 over 64x128
        int row = idx >> 5, c4 = idx & 31;
        int gr = r0 + row;
        if (gr >= n) continue;
        float4 v = *(float4*)&sA[row * LDS_PAD + c4 * 4];
        if (bias) {
            float4 b = ((const float4*)bias)[c4];
            v.x += b.x; v.y += b.y; v.z += b.z; v.w += b.w;
        }
        ((float4*)C)[gr * 32 + c4] = v;
    }
}

// ---------------- y1 = tanh(A @ hW + b1): warp per destination row --------------
__global__ void spmm_tanh(const float* __restrict__ hW, const int* __restrict__ cols,
                          const float* __restrict__ vals, const float* __restrict__ b1,
                          float* __restrict__ y1, int n)
{
    int w = (blockIdx.x * blockDim.x + threadIdx.x) >> 5;
    int lane = threadIdx.x & 31;
    if (w >= n) return;
    int s = g_rowptr[w], e = g_rowptr[w + 1];
    const float4* H = (const float4*)hW;
    float4 acc = make_float4(0.f, 0.f, 0.f, 0.f);
    int i = s;
    for (; i + 1 < e; i += 2) {
        int   c0 = __ldg(&cols[i]);
        int   c1 = __ldg(&cols[i + 1]);
        float v0 = __ldg(&vals[i]);
        float v1 = __ldg(&vals[i + 1]);
        float4 h0 = H[c0 * 32 + lane];
        float4 h1 = H[c1 * 32 + lane];
        acc.x += v0 * h0.x + v1 * h1.x;
        acc.y += v0 * h0.y + v1 * h1.y;
        acc.z += v0 * h0.z + v1 * h1.z;
        acc.w += v0 * h0.w + v1 * h1.w;
    }
    if (i < e) {
        int   c = __ldg(&cols[i]);
        float v = __ldg(&vals[i]);
        float4 h = H[c * 32 + lane];
        acc.x += v * h.x; acc.y += v * h.y; acc.z += v * h.z; acc.w += v * h.w;
    }
    float4 b = ((const float4*)b1)[lane];
    float4 o = make_float4(tanhf(acc.x + b.x), tanhf(acc.y + b.y),
                           tanhf(acc.z + b.z), tanhf(acc.w + b.w));
    ((float4*)y1)[w * 32 + lane] = o;
}

// ---------------- z = A_rel @ BN2(y1) + BN2(y1)*(ck+1)  (BN2 hoisted) -----------
__global__ void spmm_rgin(const float* __restrict__ y1, const int* __restrict__ cols,
                          const float* __restrict__ vals, const int* __restrict__ rel,
                          const float* __restrict__ relc, const float* __restrict__ ck,
                          float* __restrict__ z, int n)
{
    int w = (blockIdx.x * blockDim.x + threadIdx.x) >> 5;
    int lane = threadIdx.x & 31;
    if (w >= n) return;
    int s = g_rowptr[w], e = g_rowptr[w + 1];
    const float4* Y = (const float4*)y1;
    float4 accA = make_float4(0.f, 0.f, 0.f, 0.f);
    float  accB = 0.f;
    int i = s;
    for (; i + 1 < e; i += 2) {
        int   c0 = __ldg(&cols[i]);
        int   c1 = __ldg(&cols[i + 1]);
        float e0 = __ldg(&vals[i])     / (__ldg(&relc[__ldg(&rel[i])])     + 1.f);
        float e1 = __ldg(&vals[i + 1]) / (__ldg(&relc[__ldg(&rel[i + 1])]) + 1.f);
        float4 h0 = Y[c0 * 32 + lane];
        float4 h1 = Y[c1 * 32 + lane];
        accA.x += e0 * h0.x + e1 * h1.x;
        accA.y += e0 * h0.y + e1 * h1.y;
        accA.z += e0 * h0.z + e1 * h1.z;
        accA.w += e0 * h0.w + e1 * h1.w;
        accB += e0 + e1;
    }
    if (i < e) {
        float ev = __ldg(&vals[i]) / (__ldg(&relc[__ldg(&rel[i])]) + 1.f);
        int c = __ldg(&cols[i]);
        float4 h = Y[c * 32 + lane];
        accA.x += ev * h.x; accA.y += ev * h.y;
        accA.z += ev * h.z; accA.w += ev * h.w;
        accB += ev;
    }
    int d = lane * 4;
    float4 s2 = *(const float4*)&g_s2[d];
    float4 t2 = *(const float4*)&g_t2[d];
    float4 yr = Y[w * 32 + lane];
    float  cm = __ldg(&ck[w]) + 1.f;
    float4 o;
    o.x = s2.x * accA.x + t2.x * accB + (yr.x * s2.x + t2.x) * cm;
    o.y = s2.y * accA.y + t2.y * accB + (yr.y * s2.y + t2.y) * cm;
    o.z = s2.z * accA.z + t2.z * accB + (yr.z * s2.z + t2.z) * cm;
    o.w = s2.w * accA.w + t2.w * accB + (yr.w * s2.w + t2.w) * cm;
    ((float4*)z)[w * 32 + lane] = o;
}

// ---------------- out = l2n(concat(l2n(x), l2n(y1), l2n(y2))) -------------------
__global__ void final_norm(const float* __restrict__ x, const float* __restrict__ y1,
                           const float* __restrict__ y2, float* __restrict__ out, int n)
{
    int w = (blockIdx.x * blockDim.x + threadIdx.x) >> 5;
    int lane = threadIdx.x & 31;
    if (w >= n) return;
    float4 a = ((const float4*)x )[w * 32 + lane];
    float4 b = ((const float4*)y1)[w * 32 + lane];
    float4 c = ((const float4*)y2)[w * 32 + lane];
    float sa = a.x*a.x + a.y*a.y + a.z*a.z + a.w*a.w;
    float sb = b.x*b.x + b.y*b.y + b.z*b.z + b.w*b.w;
    float sc = c.x*c.x + c.y*c.y + c.z*c.z + c.w*c.w;
    #pragma unroll
    for (int o = 16; o; o >>= 1) {
        sa += __shfl_xor_sync(0xffffffffu, sa, o);
        sb += __shfl_xor_sync(0xffffffffu, sb, o);
        sc += __shfl_xor_sync(0xffffffffu, sc, o);
    }
    float ra = rsqrtf(fmaxf(sa, 1e-12f));
    float rb = rsqrtf(fmaxf(sb, 1e-12f));
    float rc = rsqrtf(fmaxf(sc, 1e-12f));
    float na = sa * ra * ra, nb = sb * rb * rb, nc = sc * rc * rc;
    float rt = rsqrtf(fmaxf(na + nb + nc, 1e-12f));
    float fa = ra * rt, fb = rb * rt, fc = rc * rt;
    float4* O = (float4*)out;
    int base = w * 96;
    O[base + lane]      = make_float4(a.x*fa, a.y*fa, a.z*fa, a.w*fa);
    O[base + 32 + lane] = make_float4(b.x*fb, b.y*fb, b.z*fb, b.w*fb);
    O[base + 64 + lane] = make_float4(c.x*fc, c.y*fc, c.z*fc, c.w*fc);
}

// ---------------- launch --------------------------------------------------------
extern "C" void kernel_launch(void* const* d_in, const int* in_sizes, int n_in,
                              void* d_out, int out_size)
{
    const float* x      = (const float*)d_in[0];
    const int*   rows   = (const int*)  d_in[1];
    const int*   cols   = (const int*)  d_in[2];
    const float* adj    = (const float*)d_in[3];
    const int*   rel    = (const int*)  d_in[4];
    const float* gamma1 = (const float*)d_in[5];
    const float* beta1  = (const float*)d_in[6];
    const float* mean1  = (const float*)d_in[7];
    const float* var1   = (const float*)d_in[8];
    const float* W1     = (const float*)d_in[9];
    const float* b1     = (const float*)d_in[10];
    const float* gamma2 = (const float*)d_in[11];
    const float* beta2  = (const float*)d_in[12];
    const float* mean2  = (const float*)d_in[13];
    const float* var2   = (const float*)d_in[14];
    const float* relc   = (const float*)d_in[15];
    const float* ck     = (const float*)d_in[16];
    const float* Wd     = (const float*)d_in[17];
    const float* bd     = (const float*)d_in[18];
    float* out = (float*)d_out;

    const int n = in_sizes[0] / DIM;     // 50000
    const int e = in_sizes[1];           // 640000

    cudaFuncSetAttribute(gemm128_tf32, cudaFuncAttributeMaxDynamicSharedMemorySize, GEMM_SMEM);

    // __device__ symbols are NOT valid host-side pointers — fetch device addresses.
    float *hW, *y1, *z, *y2, *s1, *t1;
    cudaGetSymbolAddress((void**)&hW, g_hW);
    cudaGetSymbolAddress((void**)&y1, g_y1);
    cudaGetSymbolAddress((void**)&z,  g_z);
    cudaGetSymbolAddress((void**)&y2, g_y2);
    cudaGetSymbolAddress((void**)&s1, g_s1);
    cudaGetSymbolAddress((void**)&t1, g_t1);

    prep_bn<<<1, DIM>>>(gamma1, beta1, mean1, var1, gamma2, beta2, mean2, var2);
    build_rowptr<<<(n + 1 + 255) / 256, 256>>>(rows, n, e);

    int gemm_blocks = (n + TM - 1) / TM;
    gemm128_tf32<<<gemm_blocks, 256, GEMM_SMEM>>>(x, W1, hW, s1, t1, nullptr, n);

    int warp_blocks = (n * 32 + 255) / 256;
    spmm_tanh<<<warp_blocks, 256>>>(hW, cols, adj, b1, y1, n);
    spmm_rgin<<<warp_blocks, 256>>>(y1, cols, adj, rel, relc, ck, z, n);

    gemm128_tf32<<<gemm_blocks, 256, GEMM_SMEM>>>(z, Wd, y2, nullptr, nullptr, bd, n);

    final_norm<<<warp_blocks, 256>>>(x, y1, y2, out, n);
}

// round 4
// speedup vs baseline: 1.3334x; 1.0677x over previous
#include <cuda_runtime.h>
#include <mma.h>
#include <math.h>

using namespace nvcuda;

// Problem constants (fixed by the dataset)
#define N_NODES 50000
#define DIM     128
#define N_EDGES 640000

// GEMM tiling: block computes 64 rows x 128 cols with tf32 wmma
#define TM 64
#define LDS_PAD 136                       // padded leading dim (mult of 8)
#define GEMM_SMEM ((DIM*LDS_PAD + TM*LDS_PAD) * 4)   // sW 69632 + sA 34816 = 104448 B

// ---------------- scratch (device globals; no allocation allowed) ----------------
__device__ float g_hW[N_NODES*DIM];
__device__ float g_y1[N_NODES*DIM];
__device__ float g_z [N_NODES*DIM];
__device__ float g_y2[N_NODES*DIM];
__device__ int   g_rowptr[N_NODES+1];
__device__ float g_s1[DIM], g_t1[DIM], g_s2[DIM], g_t2[DIM];

// -------- fused: BN folding (block 0) + rowptr build (all blocks) ---------------
__global__ void prep_all(const float* __restrict__ g1, const float* __restrict__ b1,
                         const float* __restrict__ m1, const float* __restrict__ v1,
                         const float* __restrict__ g2, const float* __restrict__ b2,
                         const float* __restrict__ m2, const float* __restrict__ v2,
                         const int* __restrict__ rows, int n, int e)
{
    if (blockIdx.x == 0 && threadIdx.x < DIM) {
        int d = threadIdx.x;
        float s1 = g1[d] * rsqrtf(v1[d] + 1e-3f);
        g_s1[d] = s1; g_t1[d] = b1[d] - m1[d] * s1;
        float s2 = g2[d] * rsqrtf(v2[d] + 1e-3f);
        g_s2[d] = s2; g_t2[d] = b2[d] - m2[d] * s2;
    }
    int r = blockIdx.x * blockDim.x + threadIdx.x;
    if (r > n) return;
    int lo = 0, hi = e;
    while (lo < hi) {
        int mid = (lo + hi) >> 1;
        if (rows[mid] < r) lo = mid + 1; else hi = mid;
    }
    g_rowptr[r] = lo;
}

// ---------------- C[n,128] = (optional BN(A)) @ W (+ optional bias), tf32 wmma --
__global__ void __launch_bounds__(256, 2)
gemm128_tf32(const float* __restrict__ A, const float* __restrict__ W,
             float* __restrict__ C,
             const float* __restrict__ bn_s, const float* __restrict__ bn_t,
             const float* __restrict__ bias, int n)
{
    extern __shared__ float sh[];
    float* sW = sh;                       // [128][136]
    float* sA = sh + DIM * LDS_PAD;       // [64][136]  (reused as epilogue buf)

    const int tid = threadIdx.x;
    const int r0  = blockIdx.x * TM;

    const float4* W4 = (const float4*)W;
    #pragma unroll
    for (int k = 0; k < 16; k++) {
        int idx = tid + k * 256;          // float4 index over 128x128
        float4 w = W4[idx];
        w.x = wmma::__float_to_tf32(w.x);
        w.y = wmma::__float_to_tf32(w.y);
        w.z = wmma::__float_to_tf32(w.z);
        w.w = wmma::__float_to_tf32(w.w);
        int row = idx >> 5, c4 = idx & 31;
        *(float4*)&sW[row * LDS_PAD + c4 * 4] = w;
    }
    #pragma unroll
    for (int k = 0; k < 8; k++) {
        int idx = tid + k * 256;
        int row = idx >> 5, c4 = idx & 31;
        int gr = r0 + row;
        float4 a = make_float4(0.f, 0.f, 0.f, 0.f);
        if (gr < n) {
            a = ((const float4*)A)[gr * 32 + c4];
            if (bn_s) {
                int d = c4 * 4;
                a.x = a.x * bn_s[d + 0] + bn_t[d + 0];
                a.y = a.y * bn_s[d + 1] + bn_t[d + 1];
                a.z = a.z * bn_s[d + 2] + bn_t[d + 2];
                a.w = a.w * bn_s[d + 3] + bn_t[d + 3];
            }
            a.x = wmma::__float_to_tf32(a.x);
            a.y = wmma::__float_to_tf32(a.y);
            a.z = wmma::__float_to_tf32(a.z);
            a.w = wmma::__float_to_tf32(a.w);
        }
        *(float4*)&sA[row * LDS_PAD + c4 * 4] = a;
    }
    __syncthreads();

    const int wid = tid >> 5;
    const int wr  = wid >> 1;            // 0..3 : 16-row group
    const int wc  = wid & 1;             // 0..1 : 64-col group

    wmma::fragment<wmma::accumulator, 16, 16, 8, float> acc[4];
    #pragma unroll
    for (int j = 0; j < 4; j++) wmma::fill_fragment(acc[j], 0.f);

    #pragma unroll
    for (int kk = 0; kk < DIM; kk += 8) {
        wmma::fragment<wmma::matrix_a, 16, 16, 8, wmma::precision::tf32, wmma::row_major> af;
        wmma::load_matrix_sync(af, &sA[(wr * 16) * LDS_PAD + kk], LDS_PAD);
        #pragma unroll
        for (int j = 0; j < 4; j++) {
            wmma::fragment<wmma::matrix_b, 16, 16, 8, wmma::precision::tf32, wmma::row_major> bf;
            wmma::load_matrix_sync(bf, &sW[kk * LDS_PAD + wc * 64 + j * 16], LDS_PAD);
            wmma::mma_sync(acc[j], af, bf, acc[j]);
        }
    }

    __syncthreads();   // everyone done reading sA
    #pragma unroll
    for (int j = 0; j < 4; j++)
        wmma::store_matrix_sync(&sA[(wr * 16) * LDS_PAD + wc * 64 + j * 16],
                                acc[j], LDS_PAD, wmma::mem_row_major);
    __syncthreads();

    #pragma unroll
    for (int k = 0; k < 8; k++) {
        int idx = tid + k * 256;          // 2048 float4 over 64x128
        int row = idx >> 5, c4 = idx & 31;
        int gr = r0 + row;
        if (gr >= n) continue;
        float4 v = *(float4*)&sA[row * LDS_PAD + c4 * 4];
        if (bias) {
            float4 b = ((const float4*)bias)[c4];
            v.x += b.x; v.y += b.y; v.z += b.z; v.w += b.w;
        }
        ((float4*)C)[gr * 32 + c4] = v;
    }
}

// ---------------- y1 = tanh(A @ hW + b1): warp per row, shfl-broadcast edges ----
__global__ void spmm_tanh(const float* __restrict__ hW, const int* __restrict__ cols,
                          const float* __restrict__ vals, const float* __restrict__ b1,
                          float* __restrict__ y1, int n)
{
    int w = (blockIdx.x * blockDim.x + threadIdx.x) >> 5;
    int lane = threadIdx.x & 31;
    if (w >= n) return;
    int s = g_rowptr[w], e = g_rowptr[w + 1];
    const float4* H = (const float4*)hW;
    float4 acc = make_float4(0.f, 0.f, 0.f, 0.f);
    for (int base = s; base < e; base += 32) {
        int idx = base + lane;
        int   cl = 0; float vl = 0.f;
        if (idx < e) { cl = __ldg(&cols[idx]); vl = __ldg(&vals[idx]); }
        int m = min(32, e - base);
        for (int j = 0; j < m; j++) {
            int   c = __shfl_sync(0xffffffffu, cl, j);
            float v = __shfl_sync(0xffffffffu, vl, j);
            float4 h = H[c * 32 + lane];
            acc.x += v * h.x; acc.y += v * h.y; acc.z += v * h.z; acc.w += v * h.w;
        }
    }
    float4 b = ((const float4*)b1)[lane];
    float4 o = make_float4(tanhf(acc.x + b.x), tanhf(acc.y + b.y),
                           tanhf(acc.z + b.z), tanhf(acc.w + b.w));
    ((float4*)y1)[w * 32 + lane] = o;
}

// ---------------- z = A_rel @ BN2(y1) + BN2(y1)*(ck+1)  (BN2 hoisted) -----------
// sum_e ev*BN2(y1[c]) = s2 * (sum ev*y1[c]) + t2 * (sum ev)
__global__ void spmm_rgin(const float* __restrict__ y1, const int* __restrict__ cols,
                          const float* __restrict__ vals, const int* __restrict__ rel,
                          const float* __restrict__ relc, const float* __restrict__ ck,
                          float* __restrict__ z, int n)
{
    int w = (blockIdx.x * blockDim.x + threadIdx.x) >> 5;
    int lane = threadIdx.x & 31;
    if (w >= n) return;
    int s = g_rowptr[w], e = g_rowptr[w + 1];
    const float4* Y = (const float4*)y1;
    float4 accA = make_float4(0.f, 0.f, 0.f, 0.f);
    float  accB = 0.f;
    for (int base = s; base < e; base += 32) {
        int idx = base + lane;
        int cl = 0; float el = 0.f;
        if (idx < e) {
            cl = __ldg(&cols[idx]);
            el = __ldg(&vals[idx]) / (__ldg(&relc[__ldg(&rel[idx])]) + 1.f);
        }
        int m = min(32, e - base);
        for (int j = 0; j < m; j++) {
            int   c  = __shfl_sync(0xffffffffu, cl, j);
            float ev = __shfl_sync(0xffffffffu, el, j);
            float4 h = Y[c * 32 + lane];
            accA.x += ev * h.x; accA.y += ev * h.y;
            accA.z += ev * h.z; accA.w += ev * h.w;
            accB += ev;
        }
    }
    int d = lane * 4;
    float4 s2 = *(const float4*)&g_s2[d];
    float4 t2 = *(const float4*)&g_t2[d];
    float4 yr = Y[w * 32 + lane];
    float  cm = __ldg(&ck[w]) + 1.f;
    float4 o;
    o.x = s2.x * accA.x + t2.x * accB + (yr.x * s2.x + t2.x) * cm;
    o.y = s2.y * accA.y + t2.y * accB + (yr.y * s2.y + t2.y) * cm;
    o.z = s2.z * accA.z + t2.z * accB + (yr.z * s2.z + t2.z) * cm;
    o.w = s2.w * accA.w + t2.w * accB + (yr.w * s2.w + t2.w) * cm;
    ((float4*)z)[w * 32 + lane] = o;
}

// ---------------- out = l2n(concat(l2n(x), l2n(y1), l2n(y2))) -------------------
__global__ void final_norm(const float* __restrict__ x, const float* __restrict__ y1,
                           const float* __restrict__ y2, float* __restrict__ out, int n)
{
    int w = (blockIdx.x * blockDim.x + threadIdx.x) >> 5;
    int lane = threadIdx.x & 31;
    if (w >= n) return;
    float4 a = ((const float4*)x )[w * 32 + lane];
    float4 b = ((const float4*)y1)[w * 32 + lane];
    float4 c = ((const float4*)y2)[w * 32 + lane];
    float sa = a.x*a.x + a.y*a.y + a.z*a.z + a.w*a.w;
    float sb = b.x*b.x + b.y*b.y + b.z*b.z + b.w*b.w;
    float sc = c.x*c.x + c.y*c.y + c.z*c.z + c.w*c.w;
    #pragma unroll
    for (int o = 16; o; o >>= 1) {
        sa += __shfl_xor_sync(0xffffffffu, sa, o);
        sb += __shfl_xor_sync(0xffffffffu, sb, o);
        sc += __shfl_xor_sync(0xffffffffu, sc, o);
    }
    float ra = rsqrtf(fmaxf(sa, 1e-12f));
    float rb = rsqrtf(fmaxf(sb, 1e-12f));
    float rc = rsqrtf(fmaxf(sc, 1e-12f));
    float na = sa * ra * ra, nb = sb * rb * rb, nc = sc * rc * rc;
    float rt = rsqrtf(fmaxf(na + nb + nc, 1e-12f));
    float fa = ra * rt, fb = rb * rt, fc = rc * rt;
    float4* O = (float4*)out;
    int base = w * 96;
    O[base + lane]      = make_float4(a.x*fa, a.y*fa, a.z*fa, a.w*fa);
    O[base + 32 + lane] = make_float4(b.x*fb, b.y*fb, b.z*fb, b.w*fb);
    O[base + 64 + lane] = make_float4(c.x*fc, c.y*fc, c.z*fc, c.w*fc);
}

// ---------------- launch --------------------------------------------------------
extern "C" void kernel_launch(void* const* d_in, const int* in_sizes, int n_in,
                              void* d_out, int out_size)
{
    const float* x      = (const float*)d_in[0];
    const int*   rows   = (const int*)  d_in[1];
    const int*   cols   = (const int*)  d_in[2];
    const float* adj    = (const float*)d_in[3];
    const int*   rel    = (const int*)  d_in[4];
    const float* gamma1 = (const float*)d_in[5];
    const float* beta1  = (const float*)d_in[6];
    const float* mean1  = (const float*)d_in[7];
    const float* var1   = (const float*)d_in[8];
    const float* W1     = (const float*)d_in[9];
    const float* b1     = (const float*)d_in[10];
    const float* gamma2 = (const float*)d_in[11];
    const float* beta2  = (const float*)d_in[12];
    const float* mean2  = (const float*)d_in[13];
    const float* var2   = (const float*)d_in[14];
    const float* relc   = (const float*)d_in[15];
    const float* ck     = (const float*)d_in[16];
    const float* Wd     = (const float*)d_in[17];
    const float* bd     = (const float*)d_in[18];
    float* out = (float*)d_out;

    const int n = in_sizes[0] / DIM;     // 50000
    const int e = in_sizes[1];           // 640000

    cudaFuncSetAttribute(gemm128_tf32, cudaFuncAttributeMaxDynamicSharedMemorySize, GEMM_SMEM);

    // __device__ symbols are NOT valid host-side pointers — fetch device addresses.
    float *hW, *y1, *z, *y2, *s1, *t1;
    cudaGetSymbolAddress((void**)&hW, g_hW);
    cudaGetSymbolAddress((void**)&y1, g_y1);
    cudaGetSymbolAddress((void**)&z,  g_z);
    cudaGetSymbolAddress((void**)&y2, g_y2);
    cudaGetSymbolAddress((void**)&s1, g_s1);
    cudaGetSymbolAddress((void**)&t1, g_t1);

    prep_all<<<(n + 1 + 255) / 256, 256>>>(gamma1, beta1, mean1, var1,
                                           gamma2, beta2, mean2, var2, rows, n, e);

    int gemm_blocks = (n + TM - 1) / TM;
    gemm128_tf32<<<gemm_blocks, 256, GEMM_SMEM>>>(x, W1, hW, s1, t1, nullptr, n);

    int warp_blocks = (n * 32 + 255) / 256;
    spmm_tanh<<<warp_blocks, 256>>>(hW, cols, adj, b1, y1, n);
    spmm_rgin<<<warp_blocks, 256>>>(y1, cols, adj, rel, relc, ck, z, n);

    gemm128_tf32<<<gemm_blocks, 256, GEMM_SMEM>>>(z, Wd, y2, nullptr, nullptr, bd, n);

    final_norm<<<warp_blocks, 256>>>(x, y1, y2, out, n);
}

// round 5
// speedup vs baseline: 1.3480x; 1.0109x over previous
#include <cuda_runtime.h>
#include <mma.h>
#include <math.h>

using namespace nvcuda;

// Problem constants (fixed by the dataset)
#define N_NODES 50000
#define DIM     128
#define N_EDGES 640000

// GEMM tiling: block computes 64 rows x 128 cols with tf32 wmma
#define TM 64
#define LDS_PAD 136                       // padded leading dim (mult of 8)
#define GEMM_SMEM ((DIM*LDS_PAD + TM*LDS_PAD) * 4)   // sW 69632 + sA 34816 = 104448 B

// ---------------- scratch (device globals; no allocation allowed) ----------------
__device__ float g_hW[N_NODES*DIM];
__device__ float g_y1[N_NODES*DIM];
__device__ float g_z [N_NODES*DIM];
__device__ float g_y2[N_NODES*DIM];
__device__ int   g_rowptr[N_NODES+1];
__device__ float g_s1[DIM], g_t1[DIM], g_s2[DIM], g_t2[DIM];

// -------- fused: BN folding (block 0) + rowptr build (all blocks) ---------------
__global__ void prep_all(const float* __restrict__ g1, const float* __restrict__ b1,
                         const float* __restrict__ m1, const float* __restrict__ v1,
                         const float* __restrict__ g2, const float* __restrict__ b2,
                         const float* __restrict__ m2, const float* __restrict__ v2,
                         const int* __restrict__ rows, int n, int e)
{
    if (blockIdx.x == 0 && threadIdx.x < DIM) {
        int d = threadIdx.x;
        float s1 = g1[d] * rsqrtf(v1[d] + 1e-3f);
        g_s1[d] = s1; g_t1[d] = b1[d] - m1[d] * s1;
        float s2 = g2[d] * rsqrtf(v2[d] + 1e-3f);
        g_s2[d] = s2; g_t2[d] = b2[d] - m2[d] * s2;
    }
    int r = blockIdx.x * blockDim.x + threadIdx.x;
    if (r > n) return;
    int lo = 0, hi = e;
    while (lo < hi) {
        int mid = (lo + hi) >> 1;
        if (rows[mid] < r) lo = mid + 1; else hi = mid;
    }
    g_rowptr[r] = lo;
}

// ---------------- C[n,128] = (optional BN(A)) @ W (+ optional bias), tf32 wmma --
__global__ void __launch_bounds__(256, 2)
gemm128_tf32(const float* __restrict__ A, const float* __restrict__ W,
             float* __restrict__ C,
             const float* __restrict__ bn_s, const float* __restrict__ bn_t,
             const float* __restrict__ bias, int n)
{
    extern __shared__ float sh[];
    float* sW = sh;                       // [128][136]
    float* sA = sh + DIM * LDS_PAD;       // [64][136]  (reused as epilogue buf)

    const int tid = threadIdx.x;
    const int r0  = blockIdx.x * TM;

    const float4* W4 = (const float4*)W;
    #pragma unroll
    for (int k = 0; k < 16; k++) {
        int idx = tid + k * 256;          // float4 index over 128x128
        float4 w = W4[idx];
        w.x = wmma::__float_to_tf32(w.x);
        w.y = wmma::__float_to_tf32(w.y);
        w.z = wmma::__float_to_tf32(w.z);
        w.w = wmma::__float_to_tf32(w.w);
        int row = idx >> 5, c4 = idx & 31;
        *(float4*)&sW[row * LDS_PAD + c4 * 4] = w;
    }
    #pragma unroll
    for (int k = 0; k < 8; k++) {
        int idx = tid + k * 256;
        int row = idx >> 5, c4 = idx & 31;
        int gr = r0 + row;
        float4 a = make_float4(0.f, 0.f, 0.f, 0.f);
        if (gr < n) {
            a = ((const float4*)A)[gr * 32 + c4];
            if (bn_s) {
                int d = c4 * 4;
                a.x = a.x * bn_s[d + 0] + bn_t[d + 0];
                a.y = a.y * bn_s[d + 1] + bn_t[d + 1];
                a.z = a.z * bn_s[d + 2] + bn_t[d + 2];
                a.w = a.w * bn_s[d + 3] + bn_t[d + 3];
            }
            a.x = wmma::__float_to_tf32(a.x);
            a.y = wmma::__float_to_tf32(a.y);
            a.z = wmma::__float_to_tf32(a.z);
            a.w = wmma::__float_to_tf32(a.w);
        }
        *(float4*)&sA[row * LDS_PAD + c4 * 4] = a;
    }
    __syncthreads();

    const int wid = tid >> 5;
    const int wr  = wid >> 1;            // 0..3 : 16-row group
    const int wc  = wid & 1;             // 0..1 : 64-col group

    wmma::fragment<wmma::accumulator, 16, 16, 8, float> acc[4];
    #pragma unroll
    for (int j = 0; j < 4; j++) wmma::fill_fragment(acc[j], 0.f);

    #pragma unroll
    for (int kk = 0; kk < DIM; kk += 8) {
        wmma::fragment<wmma::matrix_a, 16, 16, 8, wmma::precision::tf32, wmma::row_major> af;
        wmma::load_matrix_sync(af, &sA[(wr * 16) * LDS_PAD + kk], LDS_PAD);
        #pragma unroll
        for (int j = 0; j < 4; j++) {
            wmma::fragment<wmma::matrix_b, 16, 16, 8, wmma::precision::tf32, wmma::row_major> bf;
            wmma::load_matrix_sync(bf, &sW[kk * LDS_PAD + wc * 64 + j * 16], LDS_PAD);
            wmma::mma_sync(acc[j], af, bf, acc[j]);
        }
    }

    __syncthreads();   // everyone done reading sA
    #pragma unroll
    for (int j = 0; j < 4; j++)
        wmma::store_matrix_sync(&sA[(wr * 16) * LDS_PAD + wc * 64 + j * 16],
                                acc[j], LDS_PAD, wmma::mem_row_major);
    __syncthreads();

    #pragma unroll
    for (int k = 0; k < 8; k++) {
        int idx = tid + k * 256;          // 2048 float4 over 64x128
        int row = idx >> 5, c4 = idx & 31;
        int gr = r0 + row;
        if (gr >= n) continue;
        float4 v = *(float4*)&sA[row * LDS_PAD + c4 * 4];
        if (bias) {
            float4 b = ((const float4*)bias)[c4];
            v.x += b.x; v.y += b.y; v.z += b.z; v.w += b.w;
        }
        ((float4*)C)[gr * 32 + c4] = v;
    }
}

// ---------------- y1 = tanh(A @ hW + b1): warp/row, 4-deep gather pipeline ------
__global__ void spmm_tanh(const float* __restrict__ hW, const int* __restrict__ cols,
                          const float* __restrict__ vals, const float* __restrict__ b1,
                          float* __restrict__ y1, int n)
{
    int w = (blockIdx.x * blockDim.x + threadIdx.x) >> 5;
    int lane = threadIdx.x & 31;
    if (w >= n) return;
    int s = g_rowptr[w], e = g_rowptr[w + 1];
    const float4* H = (const float4*)hW;
    float4 acc = make_float4(0.f, 0.f, 0.f, 0.f);
    for (int base = s; base < e; base += 32) {
        int idx = base + lane;
        int   cl = 0; float vl = 0.f;
        if (idx < e) { cl = __ldg(&cols[idx]); vl = __ldg(&vals[idx]); }
        int m = min(32, e - base);
        int j = 0;
        for (; j + 4 <= m; j += 4) {
            int   c0 = __shfl_sync(0xffffffffu, cl, j);
            int   c1 = __shfl_sync(0xffffffffu, cl, j + 1);
            int   c2 = __shfl_sync(0xffffffffu, cl, j + 2);
            int   c3 = __shfl_sync(0xffffffffu, cl, j + 3);
            float v0 = __shfl_sync(0xffffffffu, vl, j);
            float v1 = __shfl_sync(0xffffffffu, vl, j + 1);
            float v2 = __shfl_sync(0xffffffffu, vl, j + 2);
            float v3 = __shfl_sync(0xffffffffu, vl, j + 3);
            float4 h0 = H[c0 * 32 + lane];
            float4 h1 = H[c1 * 32 + lane];
            float4 h2 = H[c2 * 32 + lane];
            float4 h3 = H[c3 * 32 + lane];
            acc.x += v0 * h0.x + v1 * h1.x + v2 * h2.x + v3 * h3.x;
            acc.y += v0 * h0.y + v1 * h1.y + v2 * h2.y + v3 * h3.y;
            acc.z += v0 * h0.z + v1 * h1.z + v2 * h2.z + v3 * h3.z;
            acc.w += v0 * h0.w + v1 * h1.w + v2 * h2.w + v3 * h3.w;
        }
        for (; j < m; j++) {
            int   c = __shfl_sync(0xffffffffu, cl, j);
            float v = __shfl_sync(0xffffffffu, vl, j);
            float4 h = H[c * 32 + lane];
            acc.x += v * h.x; acc.y += v * h.y; acc.z += v * h.z; acc.w += v * h.w;
        }
    }
    float4 b = ((const float4*)b1)[lane];
    float4 o = make_float4(tanhf(acc.x + b.x), tanhf(acc.y + b.y),
                           tanhf(acc.z + b.z), tanhf(acc.w + b.w));
    ((float4*)y1)[w * 32 + lane] = o;
}

// ---------------- z = A_rel @ BN2(y1) + BN2(y1)*(ck+1)  (BN2 hoisted) -----------
// sum_e ev*BN2(y1[c]) = s2 * (sum ev*y1[c]) + t2 * (sum ev)
__global__ void spmm_rgin(const float* __restrict__ y1, const int* __restrict__ cols,
                          const float* __restrict__ vals, const int* __restrict__ rel,
                          const float* __restrict__ relc, const float* __restrict__ ck,
                          float* __restrict__ z, int n)
{
    int w = (blockIdx.x * blockDim.x + threadIdx.x) >> 5;
    int lane = threadIdx.x & 31;
    if (w >= n) return;
    int s = g_rowptr[w], e = g_rowptr[w + 1];
    const float4* Y = (const float4*)y1;
    float4 accA = make_float4(0.f, 0.f, 0.f, 0.f);
    float  accB = 0.f;
    for (int base = s; base < e; base += 32) {
        int idx = base + lane;
        int cl = 0; float el = 0.f;
        if (idx < e) {
            cl = __ldg(&cols[idx]);
            el = __ldg(&vals[idx]) / (__ldg(&relc[__ldg(&rel[idx])]) + 1.f);
        }
        int m = min(32, e - base);
        int j = 0;
        for (; j + 4 <= m; j += 4) {
            int   c0 = __shfl_sync(0xffffffffu, cl, j);
            int   c1 = __shfl_sync(0xffffffffu, cl, j + 1);
            int   c2 = __shfl_sync(0xffffffffu, cl, j + 2);
            int   c3 = __shfl_sync(0xffffffffu, cl, j + 3);
            float e0 = __shfl_sync(0xffffffffu, el, j);
            float e1 = __shfl_sync(0xffffffffu, el, j + 1);
            float e2 = __shfl_sync(0xffffffffu, el, j + 2);
            float e3 = __shfl_sync(0xffffffffu, el, j + 3);
            float4 h0 = Y[c0 * 32 + lane];
            float4 h1 = Y[c1 * 32 + lane];
            float4 h2 = Y[c2 * 32 + lane];
            float4 h3 = Y[c3 * 32 + lane];
            accA.x += e0 * h0.x + e1 * h1.x + e2 * h2.x + e3 * h3.x;
            accA.y += e0 * h0.y + e1 * h1.y + e2 * h2.y + e3 * h3.y;
            accA.z += e0 * h0.z + e1 * h1.z + e2 * h2.z + e3 * h3.z;
            accA.w += e0 * h0.w + e1 * h1.w + e2 * h2.w + e3 * h3.w;
            accB += e0 + e1 + e2 + e3;
        }
        for (; j < m; j++) {
            int   c  = __shfl_sync(0xffffffffu, cl, j);
            float ev = __shfl_sync(0xffffffffu, el, j);
            float4 h = Y[c * 32 + lane];
            accA.x += ev * h.x; accA.y += ev * h.y;
            accA.z += ev * h.z; accA.w += ev * h.w;
            accB += ev;
        }
    }
    int d = lane * 4;
    float4 s2 = *(const float4*)&g_s2[d];
    float4 t2 = *(const float4*)&g_t2[d];
    float4 yr = Y[w * 32 + lane];
    float  cm = __ldg(&ck[w]) + 1.f;
    float4 o;
    o.x = s2.x * accA.x + t2.x * accB + (yr.x * s2.x + t2.x) * cm;
    o.y = s2.y * accA.y + t2.y * accB + (yr.y * s2.y + t2.y) * cm;
    o.z = s2.z * accA.z + t2.z * accB + (yr.z * s2.z + t2.z) * cm;
    o.w = s2.w * accA.w + t2.w * accB + (yr.w * s2.w + t2.w) * cm;
    ((float4*)z)[w * 32 + lane] = o;
}

// ---------------- out = l2n(concat(l2n(x), l2n(y1), l2n(y2))) -------------------
__global__ void final_norm(const float* __restrict__ x, const float* __restrict__ y1,
                           const float* __restrict__ y2, float* __restrict__ out, int n)
{
    int w = (blockIdx.x * blockDim.x + threadIdx.x) >> 5;
    int lane = threadIdx.x & 31;
    if (w >= n) return;
    float4 a = ((const float4*)x )[w * 32 + lane];
    float4 b = ((const float4*)y1)[w * 32 + lane];
    float4 c = ((const float4*)y2)[w * 32 + lane];
    float sa = a.x*a.x + a.y*a.y + a.z*a.z + a.w*a.w;
    float sb = b.x*b.x + b.y*b.y + b.z*b.z + b.w*b.w;
    float sc = c.x*c.x + c.y*c.y + c.z*c.z + c.w*c.w;
    #pragma unroll
    for (int o = 16; o; o >>= 1) {
        sa += __shfl_xor_sync(0xffffffffu, sa, o);
        sb += __shfl_xor_sync(0xffffffffu, sb, o);
        sc += __shfl_xor_sync(0xffffffffu, sc, o);
    }
    float ra = rsqrtf(fmaxf(sa, 1e-12f));
    float rb = rsqrtf(fmaxf(sb, 1e-12f));
    float rc = rsqrtf(fmaxf(sc, 1e-12f));
    float na = sa * ra * ra, nb = sb * rb * rb, nc = sc * rc * rc;
    float rt = rsqrtf(fmaxf(na + nb + nc, 1e-12f));
    float fa = ra * rt, fb = rb * rt, fc = rc * rt;
    float4* O = (float4*)out;
    int base = w * 96;
    O[base + lane]      = make_float4(a.x*fa, a.y*fa, a.z*fa, a.w*fa);
    O[base + 32 + lane] = make_float4(b.x*fb, b.y*fb, b.z*fb, b.w*fb);
    O[base + 64 + lane] = make_float4(c.x*fc, c.y*fc, c.z*fc, c.w*fc);
}

// ---------------- launch --------------------------------------------------------
extern "C" void kernel_launch(void* const* d_in, const int* in_sizes, int n_in,
                              void* d_out, int out_size)
{
    const float* x      = (const float*)d_in[0];
    const int*   rows   = (const int*)  d_in[1];
    const int*   cols   = (const int*)  d_in[2];
    const float* adj    = (const float*)d_in[3];
    const int*   rel    = (const int*)  d_in[4];
    const float* gamma1 = (const float*)d_in[5];
    const float* beta1  = (const float*)d_in[6];
    const float* mean1  = (const float*)d_in[7];
    const float* var1   = (const float*)d_in[8];
    const float* W1     = (const float*)d_in[9];
    const float* b1     = (const float*)d_in[10];
    const float* gamma2 = (const float*)d_in[11];
    const float* beta2  = (const float*)d_in[12];
    const float* mean2  = (const float*)d_in[13];
    const float* var2   = (const float*)d_in[14];
    const float* relc   = (const float*)d_in[15];
    const float* ck     = (const float*)d_in[16];
    const float* Wd     = (const float*)d_in[17];
    const float* bd     = (const float*)d_in[18];
    float* out = (float*)d_out;

    const int n = in_sizes[0] / DIM;     // 50000
    const int e = in_sizes[1];           // 640000

    cudaFuncSetAttribute(gemm128_tf32, cudaFuncAttributeMaxDynamicSharedMemorySize, GEMM_SMEM);

    // __device__ symbols are NOT valid host-side pointers — fetch device addresses.
    float *hW, *y1, *z, *y2, *s1, *t1;
    cudaGetSymbolAddress((void**)&hW, g_hW);
    cudaGetSymbolAddress((void**)&y1, g_y1);
    cudaGetSymbolAddress((void**)&z,  g_z);
    cudaGetSymbolAddress((void**)&y2, g_y2);
    cudaGetSymbolAddress((void**)&s1, g_s1);
    cudaGetSymbolAddress((void**)&t1, g_t1);

    prep_all<<<(n + 1 + 255) / 256, 256>>>(gamma1, beta1, mean1, var1,
                                           gamma2, beta2, mean2, var2, rows, n, e);

    int gemm_blocks = (n + TM - 1) / TM;
    gemm128_tf32<<<gemm_blocks, 256, GEMM_SMEM>>>(x, W1, hW, s1, t1, nullptr, n);

    int warp_blocks = (n * 32 + 255) / 256;
    spmm_tanh<<<warp_blocks, 256>>>(hW, cols, adj, b1, y1, n);
    spmm_rgin<<<warp_blocks, 256>>>(y1, cols, adj, rel, relc, ck, z, n);

    gemm128_tf32<<<gemm_blocks, 256, GEMM_SMEM>>>(z, Wd, y2, nullptr, nullptr, bd, n);

    final_norm<<<warp_blocks, 256>>>(x, y1, y2, out, n);
}